// round 4
// baseline (speedup 1.0000x reference)
#include <cuda_runtime.h>
#include <cuda_bf16.h>
#include <math.h>

__device__ float g_pen;
__device__ float g_cnt;
__device__ unsigned int g_done;

#define TILE_LOG 7
#define TILE (1 << TILE_LOG)   // 128 rows per warp-iteration, 4 chunks of 32

struct TileBuf {
    float2 v[4];
    float nxt_raw;   // x[(base+128)*8+3], valid on lane 31 when base+128<nrows
};

__device__ __forceinline__ void load_tile(TileBuf& b, const float* __restrict__ x,
                                          long long base, long long nrows, int lane) {
    #pragma unroll
    for (int c = 0; c < 4; c++) {
        b.v[c] = __ldcs(reinterpret_cast<const float2*>(
                     x + (base + 32LL * c + lane) * 8 + 2));
    }
    b.nxt_raw = 0.0f;
    if (lane == 31 && base + TILE < nrows) {
        b.nxt_raw = __ldcs(x + (base + TILE) * 8 + 3);
    }
}

__device__ __forceinline__ void process_tile(const TileBuf& b, long long base,
                                             long long nrows, int lane,
                                             float m2, float m3, float is2, float is3,
                                             float& pen, float& cnt) {
    float a[4];
    #pragma unroll
    for (int c = 0; c < 4; c++) a[c] = (b.v[c].y - m3) * is3;

    float an[4];
    #pragma unroll
    for (int c = 0; c < 4; c++) an[c] = __shfl_down_sync(0xffffffffu, a[c], 1);
    #pragma unroll
    for (int c = 0; c < 3; c++) {
        const float h = __shfl_sync(0xffffffffu, a[c + 1], 0);
        if (lane == 31) an[c] = h;
    }
    if (lane == 31) an[3] = (b.nxt_raw - m3) * is3;

    const bool have_nxt = (base + TILE < nrows);

    #pragma unroll
    for (int c = 0; c < 4; c++) {
        const float d = (b.v[c].x - m2) * is2;
        if (d < 0.0f || d > 252.0f)      pen += 1.0f;
        if (a[c] < 0.0f || a[c] > 22.0f) pen += 1.0f;
        if (a[c] != 22.0f)               cnt += 1.0f;

        const bool hn = (c < 3) || (lane != 31) || have_nxt;
        if (hn) {
            const bool cond = (fmodf(a[c], 2.0f) == 0.0f) && (a[c] < 20.0f);
            if (cond && (an[c] != a[c] + 1.0f) && (an[c] != 22.0f)) pen += 1.0f;
        }
    }
}

__global__ __launch_bounds__(256)
void fused_penalty_kernel(const float* __restrict__ x,
                          const float* __restrict__ min_,
                          const float* __restrict__ scale_,
                          float* __restrict__ out,
                          int out_size,
                          long long nrows,
                          int nblocks) {
    const float m2 = __ldg(min_ + 2);
    const float m3 = __ldg(min_ + 3);
    const float is2 = 1.0f / __ldg(scale_ + 2);
    const float is3 = 1.0f / __ldg(scale_ + 3);

    const int lane = threadIdx.x & 31;
    const long long wid = (long long)blockIdx.x * 8 + (threadIdx.x >> 5);
    const long long nwarps = (long long)gridDim.x * 8;
    const long long nfull = nrows >> TILE_LOG;   // full 128-row tiles

    float pen = 0.0f;
    float cnt = 0.0f;

    // ---- Software-pipelined mainloop over full tiles (double buffer) ----
    TileBuf A, B;
    long long t = wid;
    if (t < nfull) {
        load_tile(A, x, t << TILE_LOG, nrows, lane);
        for (;;) {
            long long t2 = t + nwarps;
            if (t2 < nfull) {
                load_tile(B, x, t2 << TILE_LOG, nrows, lane);
                process_tile(A, t << TILE_LOG, nrows, lane, m2, m3, is2, is3, pen, cnt);
                long long t3 = t2 + nwarps;
                if (t3 < nfull) {
                    load_tile(A, x, t3 << TILE_LOG, nrows, lane);
                    process_tile(B, t2 << TILE_LOG, nrows, lane, m2, m3, is2, is3, pen, cnt);
                    t = t3;
                    continue;
                }
                process_tile(B, t2 << TILE_LOG, nrows, lane, m2, m3, is2, is3, pen, cnt);
                break;
            }
            process_tile(A, t << TILE_LOG, nrows, lane, m2, m3, is2, is3, pen, cnt);
            break;
        }
    }

    // ---- Tail rows (nrows % 128) — only global warp 0, predicated ----
    if (wid == 0) {
        const long long tailbase = nfull << TILE_LOG;
        for (long long wb = tailbase; wb < nrows; wb += 32) {
            const long long i = wb + lane;
            const bool valid = (i < nrows);
            float d = 0.0f, a0 = 0.0f;
            if (valid) {
                const float2 v = *reinterpret_cast<const float2*>(x + i * 8 + 2);
                d  = (v.x - m2) * is2;
                a0 = (v.y - m3) * is3;
            }
            float an0 = __shfl_down_sync(0xffffffffu, a0, 1);
            const bool hn = valid && (i + 1 < nrows);
            if (lane == 31 && hn) an0 = (x[(i + 1) * 8 + 3] - m3) * is3;
            if (valid) {
                if (d < 0.0f || d > 252.0f)   pen += 1.0f;
                if (a0 < 0.0f || a0 > 22.0f)  pen += 1.0f;
                if (a0 != 22.0f)              cnt += 1.0f;
            }
            if (hn) {
                const bool cond = (fmodf(a0, 2.0f) == 0.0f) && (a0 < 20.0f);
                if (cond && (an0 != a0 + 1.0f) && (an0 != 22.0f)) pen += 1.0f;
            }
        }
    }

    // ---- Warp + block reduction ----
    #pragma unroll
    for (int off = 16; off > 0; off >>= 1) {
        pen += __shfl_down_sync(0xffffffffu, pen, off);
        cnt += __shfl_down_sync(0xffffffffu, cnt, off);
    }

    __shared__ float s_pen[8];
    __shared__ float s_cnt[8];
    const int w = threadIdx.x >> 5;
    if (lane == 0) { s_pen[w] = pen; s_cnt[w] = cnt; }
    __syncthreads();

    if (threadIdx.x == 0) {
        float bp = 0.0f, bc = 0.0f;
        #pragma unroll
        for (int k = 0; k < 8; k++) { bp += s_pen[k]; bc += s_cnt[k]; }

        atomicAdd(&g_pen, bp);
        atomicAdd(&g_cnt, bc);
        __threadfence();

        const unsigned int ticket = atomicAdd(&g_done, 1u);
        if (ticket == (unsigned int)(nblocks - 1)) {
            const float p = atomicAdd(&g_pen, 0.0f);
            const float c = atomicAdd(&g_cnt, 0.0f);
            const float result = p + fabsf(c - 58.0f);
            for (int k = 0; k < out_size; k++) out[k] = result;
            g_pen = 0.0f;
            g_cnt = 0.0f;
            __threadfence();
            g_done = 0u;
        }
    }
}

extern "C" void kernel_launch(void* const* d_in, const int* in_sizes, int n_in,
                              void* d_out, int out_size) {
    const float* x      = (const float*)d_in[0];
    const float* min_   = (const float*)d_in[1];
    const float* scale_ = (const float*)d_in[2];
    float* out = (float*)d_out;

    const long long nrows = (long long)in_sizes[0] / 8;

    // Persistent single wave: 4 blocks/SM * 148 SMs = 592 blocks.
    int blocks = 592;
    const long long nfull = nrows >> TILE_LOG;
    // Don't launch far more warps than tiles (tiny-input safety).
    long long need = (nfull + 7) / 8;
    if (need < 1) need = 1;
    if (need < blocks) blocks = (int)need;

    fused_penalty_kernel<<<blocks, 256>>>(x, min_, scale_, out, out_size,
                                          nrows, blocks);
}

// round 5
// speedup vs baseline: 1.0088x; 1.0088x over previous
#include <cuda_runtime.h>
#include <cuda_bf16.h>
#include <math.h>

__device__ float g_pen;
__device__ float g_cnt;
__device__ unsigned int g_done;

#define CHUNK_ROWS   1024
#define CHUNK_BYTES  (CHUNK_ROWS * 32)          // 32768
#define BUF_STRIDE   33024                      // 32768 + 32 (neighbor) padded to 128
#define NSTAGE       3
#define DYN_SMEM     (NSTAGE * BUF_STRIDE)      // 99072 B

__device__ __forceinline__ unsigned int smem_u32(const void* p) {
    unsigned int r;
    asm("{ .reg .u64 t; cvta.to.shared.u64 t, %1; cvt.u32.u64 %0, t; }"
        : "=r"(r) : "l"(p));
    return r;
}

__device__ __forceinline__ void mbar_init(unsigned int mbar, unsigned int cnt) {
    asm volatile("mbarrier.init.shared.b64 [%0], %1;" :: "r"(mbar), "r"(cnt) : "memory");
}

__device__ __forceinline__ void bulk_copy_issue(unsigned int dst_smem,
                                                const void* src_gmem,
                                                unsigned int bytes,
                                                unsigned int mbar) {
    asm volatile("mbarrier.arrive.expect_tx.shared.b64 _, [%0], %1;"
                 :: "r"(mbar), "r"(bytes) : "memory");
    asm volatile("cp.async.bulk.shared::cta.global.mbarrier::complete_tx::bytes "
                 "[%0], [%1], %2, [%3];"
                 :: "r"(dst_smem), "l"(src_gmem), "r"(bytes), "r"(mbar) : "memory");
}

__device__ __forceinline__ void mbar_wait(unsigned int mbar, unsigned int parity) {
    unsigned int done = 0;
    while (!done) {
        asm volatile(
            "{ .reg .pred p; "
            "mbarrier.try_wait.parity.acquire.cta.shared::cta.b64 p, [%1], %2, 0x989680; "
            "selp.b32 %0, 1, 0, p; }"
            : "=r"(done) : "r"(mbar), "r"(parity) : "memory");
    }
}

__global__ __launch_bounds__(256)
void fused_penalty_kernel(const float* __restrict__ x,
                          const float* __restrict__ min_,
                          const float* __restrict__ scale_,
                          float* __restrict__ out,
                          int out_size,
                          long long nrows,
                          int nblocks) {
    extern __shared__ __align__(128) char smem[];
    __shared__ __align__(8) unsigned long long s_mbar[NSTAGE];
    __shared__ float s_pen[8];
    __shared__ float s_cnt[8];

    const float m2 = __ldg(min_ + 2);
    const float m3 = __ldg(min_ + 3);
    const float is2 = 1.0f / __ldg(scale_ + 2);
    const float is3 = 1.0f / __ldg(scale_ + 3);

    const int tid = threadIdx.x;
    const int lane = tid & 31;
    const long long nchunks = nrows >> 10;   // full 1024-row chunks

    if (tid == 0) {
        #pragma unroll
        for (int s = 0; s < NSTAGE; s++) mbar_init(smem_u32(&s_mbar[s]), 1);
    }
    __syncthreads();

    float pen = 0.0f;
    float cnt = 0.0f;

    const long long c0 = blockIdx.x;
    if (c0 < nchunks) {
        // Prologue: issue first two chunks for this block.
        if (tid == 0) {
            #pragma unroll
            for (int s = 0; s < 2; s++) {
                const long long c = c0 + (long long)s * gridDim.x;
                if (c < nchunks) {
                    const long long base = c << 10;
                    const unsigned int extra = (base + CHUNK_ROWS < nrows) ? 32u : 0u;
                    bulk_copy_issue(smem_u32(smem + s * BUF_STRIDE),
                                    x + base * 8, CHUNK_BYTES + extra,
                                    smem_u32(&s_mbar[s]));
                }
            }
        }

        for (long long k = 0;; k++) {
            const long long ck = c0 + k * gridDim.x;
            const int buf = (int)(k % NSTAGE);
            const long long base = ck << 10;

            // Issue chunk k+2 into buffer (k+2)%NSTAGE (freed at iter k-1).
            const long long c2 = ck + 2LL * gridDim.x;
            if (tid == 0 && c2 < nchunks) {
                const long long b2 = c2 << 10;
                const unsigned int extra = (b2 + CHUNK_ROWS < nrows) ? 32u : 0u;
                const int s2 = (int)((k + 2) % NSTAGE);
                bulk_copy_issue(smem_u32(smem + s2 * BUF_STRIDE),
                                x + b2 * 8, CHUNK_BYTES + extra,
                                smem_u32(&s_mbar[s2]));
            }

            mbar_wait(smem_u32(&s_mbar[buf]), (unsigned int)((k / NSTAGE) & 1));

            const char* bp = smem + buf * BUF_STRIDE;
            #pragma unroll
            for (int s = 0; s < 4; s++) {
                const int L = s * 256 + tid;              // local row 0..1023
                const long long rg = base + L;            // global row
                const float4 v = *reinterpret_cast<const float4*>(bp + L * 32);
                const float d = (v.z - m2) * is2;
                const float a = (v.w - m3) * is3;

                float an = __shfl_down_sync(0xffffffffu, a, 1);
                const bool has_next = (rg + 1 < nrows);
                if (lane == 31 && has_next) {
                    const float c3 = *reinterpret_cast<const float*>(bp + (L + 1) * 32 + 12);
                    an = (c3 - m3) * is3;
                }

                if (d < 0.0f || d > 252.0f) pen += 1.0f;
                if (a < 0.0f || a > 22.0f)  pen += 1.0f;
                if (a != 22.0f)             cnt += 1.0f;
                if (has_next) {
                    const bool cond = (fmodf(a, 2.0f) == 0.0f) && (a < 20.0f);
                    if (cond && (an != a + 1.0f) && (an != 22.0f)) pen += 1.0f;
                }
            }

            if (ck + gridDim.x >= nchunks) break;
            __syncthreads();   // all reads of buffer (k-1)'s slot done before reuse
        }
    }

    // ---- Tail rows (nrows % 1024): block 0, warp 0, gmem path ----
    if (blockIdx.x == 0 && tid < 32) {
        const long long tailbase = nchunks << 10;
        for (long long wb = tailbase; wb < nrows; wb += 32) {
            const long long i = wb + lane;
            const bool valid = (i < nrows);
            float d = 0.0f, a0 = 0.0f;
            if (valid) {
                const float2 v = *reinterpret_cast<const float2*>(x + i * 8 + 2);
                d  = (v.x - m2) * is2;
                a0 = (v.y - m3) * is3;
            }
            float an0 = __shfl_down_sync(0xffffffffu, a0, 1);
            const bool hn = valid && (i + 1 < nrows);
            if (lane == 31 && hn) an0 = (x[(i + 1) * 8 + 3] - m3) * is3;
            if (valid) {
                if (d < 0.0f || d > 252.0f)  pen += 1.0f;
                if (a0 < 0.0f || a0 > 22.0f) pen += 1.0f;
                if (a0 != 22.0f)             cnt += 1.0f;
            }
            if (hn) {
                const bool cond = (fmodf(a0, 2.0f) == 0.0f) && (a0 < 20.0f);
                if (cond && (an0 != a0 + 1.0f) && (an0 != 22.0f)) pen += 1.0f;
            }
        }
    }

    // ---- Warp + block reduction, ticketed finalize ----
    #pragma unroll
    for (int off = 16; off > 0; off >>= 1) {
        pen += __shfl_down_sync(0xffffffffu, pen, off);
        cnt += __shfl_down_sync(0xffffffffu, cnt, off);
    }
    __syncthreads();   // re-sync all threads before shared reuse
    const int w = tid >> 5;
    if (lane == 0) { s_pen[w] = pen; s_cnt[w] = cnt; }
    __syncthreads();

    if (tid == 0) {
        float bpn = 0.0f, bcn = 0.0f;
        #pragma unroll
        for (int k = 0; k < 8; k++) { bpn += s_pen[k]; bcn += s_cnt[k]; }

        atomicAdd(&g_pen, bpn);
        atomicAdd(&g_cnt, bcn);
        __threadfence();

        const unsigned int ticket = atomicAdd(&g_done, 1u);
        if (ticket == (unsigned int)(nblocks - 1)) {
            const float p = atomicAdd(&g_pen, 0.0f);
            const float c = atomicAdd(&g_cnt, 0.0f);
            const float result = p + fabsf(c - 58.0f);
            for (int k = 0; k < out_size; k++) out[k] = result;
            g_pen = 0.0f;
            g_cnt = 0.0f;
            __threadfence();
            g_done = 0u;
        }
    }
}

extern "C" void kernel_launch(void* const* d_in, const int* in_sizes, int n_in,
                              void* d_out, int out_size) {
    const float* x      = (const float*)d_in[0];
    const float* min_   = (const float*)d_in[1];
    const float* scale_ = (const float*)d_in[2];
    float* out = (float*)d_out;

    const long long nrows = (long long)in_sizes[0] / 8;
    const long long nchunks = nrows >> 10;

    cudaFuncSetAttribute(fused_penalty_kernel,
                         cudaFuncAttributeMaxDynamicSharedMemorySize, DYN_SMEM);

    long long blocks_ll = 296;                 // 2 blocks/SM persistent
    if (nchunks > 0 && nchunks < blocks_ll) blocks_ll = nchunks;
    if (nchunks == 0) blocks_ll = 1;
    const int blocks = (int)blocks_ll;

    fused_penalty_kernel<<<blocks, 256, DYN_SMEM>>>(x, min_, scale_, out,
                                                    out_size, nrows, blocks);
}

// round 6
// speedup vs baseline: 1.0862x; 1.0767x over previous
#include <cuda_runtime.h>
#include <cuda_bf16.h>
#include <math.h>

__device__ float g_pen;
__device__ float g_cnt;
__device__ unsigned int g_done;

// Non-coherent load with 256B L2 fetch-granule hint (batches DRAM sector
// requests 8-at-a-time along the stream). Non-volatile: pure load, lets
// ptxas batch/hoist all 8 per tile.
__device__ __forceinline__ float2 ldg_nc256_f2(const float* p) {
    float2 v;
    asm("ld.global.nc.L2::256B.v2.f32 {%0,%1}, [%2];"
        : "=f"(v.x), "=f"(v.y) : "l"(p));
    return v;
}
__device__ __forceinline__ float ldg_nc256_f(const float* p) {
    float v;
    asm("ld.global.nc.L2::256B.f32 %0, [%1];" : "=f"(v) : "l"(p));
    return v;
}

// fmod(a,2)==0  <=>  a*0.5 == floor(a*0.5)  (x0.5 exact; equality only for
// exact even integers, including negatives; NaN fails both sides).
__device__ __forceinline__ bool is_even_int(float a) {
    const float h = a * 0.5f;
    return h == floorf(h);
}

// Each warp owns a contiguous 256-row tile: 8 chunks of 32 rows.
__global__ __launch_bounds__(256)
void fused_penalty_kernel(const float* __restrict__ x,
                          const float* __restrict__ min_,
                          const float* __restrict__ scale_,
                          float* __restrict__ out,
                          int out_size,
                          long long nrows,
                          int nblocks) {
    const float m2 = __ldg(min_ + 2);
    const float m3 = __ldg(min_ + 3);
    const float is2 = 1.0f / __ldg(scale_ + 2);
    const float is3 = 1.0f / __ldg(scale_ + 3);

    const int lane = threadIdx.x & 31;
    const int wpb = blockDim.x >> 5;
    const long long wid = (long long)blockIdx.x * wpb + (threadIdx.x >> 5);
    const long long nwarps = (long long)gridDim.x * wpb;
    const long long ntiles = (nrows + 255) >> 8;

    float pen = 0.0f;
    float cnt = 0.0f;

    for (long long t = wid; t < ntiles; t += nwarps) {
        const long long base = t << 8;

        if (base + 256 <= nrows) {
            // ---- Full tile: 8 front-batched hinted loads ----
            float2 v[8];
            #pragma unroll
            for (int c = 0; c < 8; c++) {
                v[c] = ldg_nc256_f2(x + (base + 32LL * c + lane) * 8 + 2);
            }

            const bool have_nxt = (base + 256 < nrows);
            float nxt_a = 0.0f;
            if (lane == 31 && have_nxt) {
                nxt_a = (ldg_nc256_f(x + (base + 256) * 8 + 3) - m3) * is3;
            }

            float a[8];
            #pragma unroll
            for (int c = 0; c < 8; c++) a[c] = (v[c].y - m3) * is3;

            float an[8];
            #pragma unroll
            for (int c = 0; c < 8; c++)
                an[c] = __shfl_down_sync(0xffffffffu, a[c], 1);
            #pragma unroll
            for (int c = 0; c < 7; c++) {
                const float h = __shfl_sync(0xffffffffu, a[c + 1], 0);
                if (lane == 31) an[c] = h;
            }
            if (lane == 31) an[7] = nxt_a;

            const bool last_ok = (lane != 31) || have_nxt;

            #pragma unroll
            for (int c = 0; c < 8; c++) {
                const float d = (v[c].x - m2) * is2;
                if (d < 0.0f || d > 252.0f)      pen += 1.0f;
                if (a[c] < 0.0f || a[c] > 22.0f) pen += 1.0f;
                if (a[c] != 22.0f)               cnt += 1.0f;

                const bool hn = (c < 7) || last_ok;
                if (hn && is_even_int(a[c]) && (a[c] < 20.0f)
                       && (an[c] != a[c] + 1.0f) && (an[c] != 22.0f))
                    pen += 1.0f;
            }
        } else {
            // ---- Partial tail tile: predicated scalar path ----
            #pragma unroll
            for (int c = 0; c < 8; c++) {
                const long long i = base + 32LL * c + lane;
                const bool valid = (i < nrows);
                float d = 0.0f, a0 = 0.0f;
                if (valid) {
                    const float2 vv = *reinterpret_cast<const float2*>(x + i * 8 + 2);
                    d  = (vv.x - m2) * is2;
                    a0 = (vv.y - m3) * is3;
                }
                float an0 = __shfl_down_sync(0xffffffffu, a0, 1);
                const bool hn = valid && (i + 1 < nrows);
                if (lane == 31 && hn) {
                    an0 = (x[(i + 1) * 8 + 3] - m3) * is3;
                }
                if (valid) {
                    if (d < 0.0f || d > 252.0f)   pen += 1.0f;
                    if (a0 < 0.0f || a0 > 22.0f)  pen += 1.0f;
                    if (a0 != 22.0f)              cnt += 1.0f;
                }
                if (hn && is_even_int(a0) && (a0 < 20.0f)
                       && (an0 != a0 + 1.0f) && (an0 != 22.0f))
                    pen += 1.0f;
            }
        }
    }

    // ---- Warp reduction ----
    #pragma unroll
    for (int off = 16; off > 0; off >>= 1) {
        pen += __shfl_down_sync(0xffffffffu, pen, off);
        cnt += __shfl_down_sync(0xffffffffu, cnt, off);
    }

    __shared__ float s_pen[8];
    __shared__ float s_cnt[8];
    const int w = threadIdx.x >> 5;
    if (lane == 0) { s_pen[w] = pen; s_cnt[w] = cnt; }
    __syncthreads();

    if (threadIdx.x == 0) {
        float bp = 0.0f, bc = 0.0f;
        #pragma unroll
        for (int k = 0; k < 8; k++) { bp += s_pen[k]; bc += s_cnt[k]; }

        atomicAdd(&g_pen, bp);
        atomicAdd(&g_cnt, bc);
        __threadfence();

        const unsigned int ticket = atomicAdd(&g_done, 1u);
        if (ticket == (unsigned int)(nblocks - 1)) {
            const float p = atomicAdd(&g_pen, 0.0f);
            const float c = atomicAdd(&g_cnt, 0.0f);
            const float result = p + fabsf(c - 58.0f);
            for (int k = 0; k < out_size; k++) out[k] = result;
            g_pen = 0.0f;
            g_cnt = 0.0f;
            __threadfence();
            g_done = 0u;
        }
    }
}

extern "C" void kernel_launch(void* const* d_in, const int* in_sizes, int n_in,
                              void* d_out, int out_size) {
    const float* x      = (const float*)d_in[0];
    const float* min_   = (const float*)d_in[1];
    const float* scale_ = (const float*)d_in[2];
    float* out = (float*)d_out;

    const long long nrows = (long long)in_sizes[0] / 8;
    const long long ntiles = (nrows + 255) >> 8;

    // 8 warps/block; one tile per warp when the grid covers all tiles.
    long long blocks_ll = (ntiles + 7) / 8;
    if (blocks_ll < 1) blocks_ll = 1;
    if (blocks_ll > 2048) blocks_ll = 2048;
    const int blocks = (int)blocks_ll;

    fused_penalty_kernel<<<blocks, 256>>>(x, min_, scale_, out, out_size,
                                          nrows, blocks);
}